// round 9
// baseline (speedup 1.0000x reference)
#include <cuda_runtime.h>
#include <cstdint>

#define B_    2
#define S_    1024
#define HQ_   32
#define HKV_  8
#define D_    128
#define BQ    128
#define BK    64
#define NT    256
#define QSTR  132
#define KSTR  132
#define VSTR  136
#define PSTR  36

// smem word offsets
#define W_Q    0          // 128*132 = 16896
#define W_K    16896      // 64*132  = 8448
#define W_V    25344      // 64*136  = 8704
#define W_P    34048      // 8 warps * 32 rows * 36 = 9216
#define W_MLX  43264      // 128*2
#define W_TOT  43520      // 174,080 bytes

static __device__ __forceinline__ uint32_t f2tf(float x) {
    uint32_t u; asm("cvt.rna.tf32.f32 %0, %1;" : "=r"(u) : "f"(x)); return u;
}
static __device__ __forceinline__ void mma8(float* d, const uint32_t* a,
                                            uint32_t b0, uint32_t b1) {
    asm volatile(
        "mma.sync.aligned.m16n8k8.row.col.f32.tf32.tf32.f32 "
        "{%0,%1,%2,%3}, {%4,%5,%6,%7}, {%8,%9}, {%0,%1,%2,%3};"
        : "+f"(d[0]), "+f"(d[1]), "+f"(d[2]), "+f"(d[3])
        : "r"(a[0]), "r"(a[1]), "r"(a[2]), "r"(a[3]), "r"(b0), "r"(b1));
}
static __device__ __forceinline__ uint4 cvt4(float4 v) {
    uint4 u; u.x = f2tf(v.x); u.y = f2tf(v.y); u.z = f2tf(v.z); u.w = f2tf(v.w);
    return u;
}

// -------------------------------------------------------------------------
// KV-cache scatter (unchanged — negligible)
// -------------------------------------------------------------------------
__global__ void kv_scatter_kernel(const float* __restrict__ xk,
                                  const float* __restrict__ xv,
                                  const int* __restrict__ idx,
                                  float* __restrict__ kvout) {
    int t = blockIdx.x * blockDim.x + threadIdx.x;
    const int total = B_ * S_ * 2 * HKV_ * (D_ / 4);
    if (t >= total) return;
    int d4 = t & 31;
    int hh = (t >> 5) & 15;
    int i  = t >> 9;
    float4 v;
    if (hh < HKV_)
        v = reinterpret_cast<const float4*>(xk)[(i * HKV_ + hh) * 32 + d4];
    else
        v = reinterpret_cast<const float4*>(xv)[(i * HKV_ + (hh - HKV_)) * 32 + d4];
    int row = idx[i];
    reinterpret_cast<float4*>(kvout)[((size_t)row * 16 + hh) * 32 + d4] = v;
}

// -------------------------------------------------------------------------
// M-blocked split-K tf32 flash attention.
// BQ=128 q rows, 8 warps: wq=w>>1 owns 32 q rows (two m16 fragments);
// wk=w&1 owns keys wk*32..+31 of each 64-key tile. Each B-fragment pair
// feeds 2 mmas (halved B-operand crossbar bytes per mma). Fully private
// online-softmax chains (4 per thread); two-way flash merge at the end.
// Warp-private P buffer, PSTR=36 (conflict-free A-fragment loads).
// -------------------------------------------------------------------------
__global__ __launch_bounds__(NT, 1)
void attn_mma(const float* __restrict__ xq, const float* __restrict__ xk,
              const float* __restrict__ xv, float* __restrict__ out) {
    extern __shared__ uint32_t sm[];
    float* mlx  = (float*)(sm + W_MLX);
    float* Ored = (float*)(sm + W_Q);     // epilogue alias over Qs

    const int tid = threadIdx.x, w = tid >> 5, lane = tid & 31;
    const int wq = w >> 1, wk = w & 1;
    const int g = lane >> 2, t = lane & 3;
    const int qt = (S_ / BQ - 1) - blockIdx.x;   // big tiles first
    const int h = blockIdx.y, b = blockIdx.z, hk = h >> 2;
    const int m0 = wq * 32, ko = wk * 32;
    const float scale = 0.08838834764831845f;    // 1/sqrt(128)
    const uint32_t pw = W_P + w * 1152;          // 32*36 words per warp

    // ---- Q tile: global -> smem (scaled, tf32) ----
#pragma unroll
    for (int i = 0; i < 16; ++i) {
        int it = tid + i * NT;
        int r = it >> 5, c4 = (it & 31) << 2;
        float4 v = *reinterpret_cast<const float4*>(
            xq + ((((size_t)b * S_ + (size_t)qt * BQ + r) * HQ_ + h) * D_ + c4));
        v.x *= scale; v.y *= scale; v.z *= scale; v.w *= scale;
        *reinterpret_cast<uint4*>(sm + W_Q + r * QSTR + c4) = cvt4(v);
    }

    float Oa[2][16][4];
#pragma unroll
    for (int mf = 0; mf < 2; ++mf)
#pragma unroll
        for (int n = 0; n < 16; ++n)
#pragma unroll
            for (int c = 0; c < 4; ++c) Oa[mf][n][c] = 0.0f;
    float mr[2][2] = {{-1e30f, -1e30f}, {-1e30f, -1e30f}};
    float lr[2][2] = {{0.0f, 0.0f}, {0.0f, 0.0f}};

    const int n64 = 2 * qt + 2;
    for (int kt = 0; kt < n64; ++kt) {
        __syncthreads();   // B1: prior tile's K/V readers done (kt=0: Q stores)

        // ---- K,V tile: global -> smem (tf32) ----
#pragma unroll
        for (int i = 0; i < 8; ++i) {
            int it = tid + i * NT;
            int r = it >> 5, c4 = (it & 31) << 2;
            size_t ga = (((size_t)b * S_ + (size_t)kt * BK + r) * HKV_ + hk) * D_ + c4;
            *reinterpret_cast<uint4*>(sm + W_K + r * KSTR + c4) =
                cvt4(*reinterpret_cast<const float4*>(xk + ga));
            *reinterpret_cast<uint4*>(sm + W_V + r * VSTR + c4) =
                cvt4(*reinterpret_cast<const float4*>(xv + ga));
        }
        __syncthreads();   // B2: K/V visible

        // ---- QK^T on own 32-key slice, 32 q rows: S(32x32) ----
        float Sa[2][4][4];
#pragma unroll
        for (int mf = 0; mf < 2; ++mf)
#pragma unroll
            for (int n = 0; n < 4; ++n)
#pragma unroll
                for (int c = 0; c < 4; ++c) Sa[mf][n][c] = 0.0f;
#pragma unroll
        for (int kk = 0; kk < 16; ++kk) {
            const uint32_t* qp0 = sm + W_Q + (m0 + g) * QSTR + kk * 8 + t;
            uint32_t qa0[4] = {qp0[0], qp0[8 * QSTR], qp0[4], qp0[8 * QSTR + 4]};
            const uint32_t* qp1 = qp0 + 16 * QSTR;
            uint32_t qa1[4] = {qp1[0], qp1[8 * QSTR], qp1[4], qp1[8 * QSTR + 4]};
#pragma unroll
            for (int n = 0; n < 4; ++n) {
                const uint32_t* kb = sm + W_K + (ko + n * 8 + g) * KSTR + kk * 8 + t;
                uint32_t b0 = kb[0], b1 = kb[4];
                mma8(Sa[0][n], qa0, b0, b1);   // one B pair feeds two mmas
                mma8(Sa[1][n], qa1, b0, b1);
            }
        }

        // ---- causal mask (last two tiles straddle the diagonal) ----
        if (kt >= 2 * qt) {
            const int gc0 = kt * BK + ko;
#pragma unroll
            for (int mf = 0; mf < 2; ++mf) {
                const int grow = qt * BQ + m0 + 16 * mf + g;
#pragma unroll
                for (int n = 0; n < 4; ++n) {
                    int c = gc0 + n * 8 + 2 * t;
                    if (c     > grow)     Sa[mf][n][0] = -1e30f;
                    if (c + 1 > grow)     Sa[mf][n][1] = -1e30f;
                    if (c     > grow + 8) Sa[mf][n][2] = -1e30f;
                    if (c + 1 > grow + 8) Sa[mf][n][3] = -1e30f;
                }
            }
        }

        // ---- private online softmax: 4 chains (mf, j) ----
        float mx[2][2] = {{-1e30f, -1e30f}, {-1e30f, -1e30f}};
#pragma unroll
        for (int mf = 0; mf < 2; ++mf)
#pragma unroll
            for (int n = 0; n < 4; ++n) {
                mx[mf][0] = fmaxf(mx[mf][0], fmaxf(Sa[mf][n][0], Sa[mf][n][1]));
                mx[mf][1] = fmaxf(mx[mf][1], fmaxf(Sa[mf][n][2], Sa[mf][n][3]));
            }
        float f[2][2];
#pragma unroll
        for (int mf = 0; mf < 2; ++mf)
#pragma unroll
            for (int j = 0; j < 2; ++j) {
                float v = mx[mf][j];
                v = fmaxf(v, __shfl_xor_sync(0xffffffffu, v, 1));
                v = fmaxf(v, __shfl_xor_sync(0xffffffffu, v, 2));
                float M = fmaxf(mr[mf][j], v);
                f[mf][j] = __expf(mr[mf][j] - M);
                mr[mf][j] = M;
            }

        float s[2][2] = {{0.0f, 0.0f}, {0.0f, 0.0f}};
#pragma unroll
        for (int mf = 0; mf < 2; ++mf) {
            uint32_t pr0 = pw + (16 * mf + g) * PSTR + 2 * t;
            uint32_t pr1 = pr0 + 8 * PSTR;
#pragma unroll
            for (int n = 0; n < 4; ++n) {
                float p00 = __expf(Sa[mf][n][0] - mr[mf][0]);
                float p01 = __expf(Sa[mf][n][1] - mr[mf][0]);
                float p10 = __expf(Sa[mf][n][2] - mr[mf][1]);
                float p11 = __expf(Sa[mf][n][3] - mr[mf][1]);
                s[mf][0] += p00 + p01; s[mf][1] += p10 + p11;
                sm[pr0 + n * 8]     = f2tf(p00);
                sm[pr0 + n * 8 + 1] = f2tf(p01);
                sm[pr1 + n * 8]     = f2tf(p10);
                sm[pr1 + n * 8 + 1] = f2tf(p11);
            }
        }
#pragma unroll
        for (int mf = 0; mf < 2; ++mf)
#pragma unroll
            for (int j = 0; j < 2; ++j) {
                float v = s[mf][j];
                v += __shfl_xor_sync(0xffffffffu, v, 1);
                v += __shfl_xor_sync(0xffffffffu, v, 2);
                lr[mf][j] = lr[mf][j] * f[mf][j] + v;
            }
        __syncwarp();      // P is warp-private

        // ---- rescale O; PV on own 32-key slice ----
#pragma unroll
        for (int mf = 0; mf < 2; ++mf)
#pragma unroll
            for (int n = 0; n < 16; ++n) {
                Oa[mf][n][0] *= f[mf][0]; Oa[mf][n][1] *= f[mf][0];
                Oa[mf][n][2] *= f[mf][1]; Oa[mf][n][3] *= f[mf][1];
            }
#pragma unroll
        for (int kk = 0; kk < 4; ++kk) {
            const uint32_t* p0 = sm + pw + g * PSTR + kk * 8 + t;
            uint32_t af0[4] = {p0[0], p0[8 * PSTR], p0[4], p0[8 * PSTR + 4]};
            const uint32_t* p1 = p0 + 16 * PSTR;
            uint32_t af1[4] = {p1[0], p1[8 * PSTR], p1[4], p1[8 * PSTR + 4]};
#pragma unroll
            for (int n = 0; n < 16; ++n) {
                const uint32_t* vb = sm + W_V + (ko + kk * 8 + t) * VSTR + n * 8 + g;
                uint32_t b0 = vb[0], b1 = vb[4 * VSTR];
                mma8(Oa[0][n], af0, b0, b1);
                mma8(Oa[1][n], af1, b0, b1);
            }
        }
    }

    // ---- epilogue: two-way flash merge of the private key-halves ----
    __syncthreads();       // main loop done; Qs dead -> reuse as Ored
    if (wk == 1) {
#pragma unroll
        for (int mf = 0; mf < 2; ++mf) {
            const int r0 = m0 + 16 * mf + g;
#pragma unroll
            for (int n = 0; n < 16; ++n) {
                int col = n * 8 + 2 * t;
                Ored[r0 * 132 + col]           = Oa[mf][n][0];
                Ored[r0 * 132 + col + 1]       = Oa[mf][n][1];
                Ored[(r0 + 8) * 132 + col]     = Oa[mf][n][2];
                Ored[(r0 + 8) * 132 + col + 1] = Oa[mf][n][3];
            }
            if (t == 0) {
                mlx[2 * r0]           = mr[mf][0];
                mlx[2 * r0 + 1]       = lr[mf][0];
                mlx[2 * (r0 + 8)]     = mr[mf][1];
                mlx[2 * (r0 + 8) + 1] = lr[mf][1];
            }
        }
    }
    __syncthreads();
    if (wk == 0) {
#pragma unroll
        for (int mf = 0; mf < 2; ++mf) {
#pragma unroll
            for (int j = 0; j < 2; ++j) {
                const int r = m0 + 16 * mf + g + 8 * j;
                const float m1 = mlx[2 * r], l1 = mlx[2 * r + 1];
                const float M = fmaxf(mr[mf][j], m1);
                const float c0 = __expf(mr[mf][j] - M), c1 = __expf(m1 - M);
                const float inv = 1.0f / (lr[mf][j] * c0 + l1 * c1);
                float* ob = out + (((size_t)b * S_ + (size_t)qt * BQ + r) * HQ_ + h) * D_;
#pragma unroll
                for (int n = 0; n < 16; ++n) {
                    int col = n * 8 + 2 * t;
                    float2 o;
                    o.x = (Oa[mf][n][2 * j]     * c0 + Ored[r * 132 + col]     * c1) * inv;
                    o.y = (Oa[mf][n][2 * j + 1] * c0 + Ored[r * 132 + col + 1] * c1) * inv;
                    *reinterpret_cast<float2*>(ob + col) = o;
                }
            }
        }
    }
}

// -------------------------------------------------------------------------
extern "C" void kernel_launch(void* const* d_in, const int* in_sizes, int n_in,
                              void* d_out, int out_size) {
    const float* xq    = (const float*)d_in[0];
    const float* xk    = (const float*)d_in[1];
    const float* xv    = (const float*)d_in[2];
    const float* kvbuf = (const float*)d_in[3];
    const int*   idx   = (const int*)d_in[4];

    float* out   = (float*)d_out;
    float* kvout = out + (size_t)B_ * S_ * HQ_ * D_;

    cudaMemcpyAsync(kvout, kvbuf, (size_t)B_ * S_ * 2 * HKV_ * D_ * sizeof(float),
                    cudaMemcpyDeviceToDevice, 0);
    const int nvec = B_ * S_ * 2 * HKV_ * (D_ / 4);
    kv_scatter_kernel<<<(nvec + 255) / 256, 256>>>(xk, xv, idx, kvout);

    const int smem_bytes = W_TOT * (int)sizeof(uint32_t);   // 174,080
    cudaFuncSetAttribute(attn_mma,
                         cudaFuncAttributeMaxDynamicSharedMemorySize, smem_bytes);
    attn_mma<<<dim3(S_ / BQ, HQ_, B_), NT, smem_bytes>>>(xq, xk, xv, out);
}

// round 10
// speedup vs baseline: 1.6714x; 1.6714x over previous
#include <cuda_runtime.h>
#include <cstdint>

#define B_    2
#define S_    1024
#define HQ_   32
#define HKV_  8
#define D_    128
#define BQ    128
#define BK    128
#define NT    512
#define QS    68     // Qh/Kh row stride in u32 words (64 d-pairs + pad)
#define VTS   68     // Vt row stride (64 key-pairs + pad)
#define PSTR  36     // P row stride (32 key-pairs + pad)

// smem u32-word offsets
#define W_Q    0         // 128*68 = 8704
#define W_K    8704      // 8704
#define W_V    17408     // 8704 (Vt: 128 d-rows x 68)
#define W_P    26112     // 16 warps * 16 rows * 36 = 9216
#define W_MLX  35328     // 256
#define W_TOT  35584     // 142,336 bytes

static __device__ __forceinline__ uint32_t pack2(float lo, float hi) {
    uint32_t d;
    asm("cvt.rn.f16x2.f32 %0, %1, %2;" : "=r"(d) : "f"(hi), "f"(lo));
    return d;
}
static __device__ __forceinline__ void mma16(float* d, const uint32_t* a,
                                             uint32_t b0, uint32_t b1) {
    asm volatile(
        "mma.sync.aligned.m16n8k16.row.col.f32.f16.f16.f32 "
        "{%0,%1,%2,%3}, {%4,%5,%6,%7}, {%8,%9}, {%0,%1,%2,%3};"
        : "+f"(d[0]), "+f"(d[1]), "+f"(d[2]), "+f"(d[3])
        : "r"(a[0]), "r"(a[1]), "r"(a[2]), "r"(a[3]), "r"(b0), "r"(b1));
}

// -------------------------------------------------------------------------
// KV-cache scatter (unchanged — negligible)
// -------------------------------------------------------------------------
__global__ void kv_scatter_kernel(const float* __restrict__ xk,
                                  const float* __restrict__ xv,
                                  const int* __restrict__ idx,
                                  float* __restrict__ kvout) {
    int t = blockIdx.x * blockDim.x + threadIdx.x;
    const int total = B_ * S_ * 2 * HKV_ * (D_ / 4);
    if (t >= total) return;
    int d4 = t & 31;
    int hh = (t >> 5) & 15;
    int i  = t >> 9;
    float4 v;
    if (hh < HKV_)
        v = reinterpret_cast<const float4*>(xk)[(i * HKV_ + hh) * 32 + d4];
    else
        v = reinterpret_cast<const float4*>(xv)[(i * HKV_ + (hh - HKV_)) * 32 + d4];
    int row = idx[i];
    reinterpret_cast<float4*>(kvout)[((size_t)row * 16 + hh) * 32 + d4] = v;
}

// -------------------------------------------------------------------------
// fp16 m16n8k16 split-K flash attention (R5 structure, half the bytes).
// 16 warps: wq=w>>1 owns q rows 16*wq..+15; wk=w&1 owns keys wk*64..+63.
// Qh/Kh: [row][d-pair f16x2], stride 68. Vt: transposed [d][key-pair f16x2],
// stride 68 (PV contracts over keys). P: warp-private [16][36] f16x2.
// Private online-softmax chains; two-way flash merge epilogue.
// 2 __syncthreads per tile.
// -------------------------------------------------------------------------
__global__ __launch_bounds__(NT, 1)
void attn_mma(const float* __restrict__ xq, const float* __restrict__ xk,
              const float* __restrict__ xv, float* __restrict__ out) {
    extern __shared__ uint32_t sm[];
    float* mlx  = (float*)(sm + W_MLX);
    float* Ored = (float*)(sm + W_Q);     // epilogue alias over Qh+Kh

    const int tid = threadIdx.x, w = tid >> 5, lane = tid & 31;
    const int wq = w >> 1, wk = w & 1;
    const int g = lane >> 2, t = lane & 3;
    const int qt = (S_ / BQ - 1) - blockIdx.x;   // big tiles first
    const int h = blockIdx.y, b = blockIdx.z, hk = h >> 2;
    const int m0 = wq * 16, ko = wk * 64;
    const int r0loc = m0 + g, r1loc = m0 + g + 8;
    const float scale = 0.08838834764831845f;    // 1/sqrt(128)
    const uint32_t pw = W_P + w * 576;           // warp-private P

    // ---- Q tile: global -> f16x2 pairs (scaled) ----
#pragma unroll
    for (int i = 0; i < 8; ++i) {
        int it = tid + i * NT;
        int r = it >> 5, c4 = it & 31;
        float4 v = *reinterpret_cast<const float4*>(
            xq + ((((size_t)b * S_ + (size_t)qt * BQ + r) * HQ_ + h) * D_ + c4 * 4));
        uint2 u;
        u.x = pack2(v.x * scale, v.y * scale);
        u.y = pack2(v.z * scale, v.w * scale);
        *reinterpret_cast<uint2*>(sm + W_Q + r * QS + c4 * 2) = u;
    }

    float Oa[16][4];
#pragma unroll
    for (int n = 0; n < 16; ++n)
#pragma unroll
        for (int c = 0; c < 4; ++c) Oa[n][c] = 0.0f;
    float mr0 = -1e30f, mr1 = -1e30f, lr0 = 0.0f, lr1 = 0.0f;

    for (int kt = 0; kt <= qt; ++kt) {
        __syncthreads();   // B1: prior tile's Kh/Vt readers done (kt=0: Q)

        // ---- K tile: [key][d-pair] ----
#pragma unroll
        for (int i = 0; i < 8; ++i) {
            int it = tid + i * NT;
            int r = it >> 5, c4 = it & 31;
            size_t ga = (((size_t)b * S_ + (size_t)kt * BK + r) * HKV_ + hk) * D_
                        + c4 * 4;
            float4 v = *reinterpret_cast<const float4*>(xk + ga);
            uint2 u;
            u.x = pack2(v.x, v.y);
            u.y = pack2(v.z, v.w);
            *reinterpret_cast<uint2*>(sm + W_K + r * QS + c4 * 2) = u;
        }
        // ---- V tile transposed: Vt[d][key-pair] (key-pair-major tasks) ----
#pragma unroll
        for (int i = 0; i < 4; ++i) {
            int task = tid + i * NT;           // 2048 tasks
            int kp = task & 63, dq = task >> 6;
            size_t ga = (((size_t)b * S_ + (size_t)kt * BK + 2 * kp) * HKV_ + hk) * D_
                        + dq * 4;
            float4 va = *reinterpret_cast<const float4*>(xv + ga);
            float4 vb = *reinterpret_cast<const float4*>(xv + ga + (size_t)HKV_ * D_);
            sm[W_V + (4 * dq + 0) * VTS + kp] = pack2(va.x, vb.x);
            sm[W_V + (4 * dq + 1) * VTS + kp] = pack2(va.y, vb.y);
            sm[W_V + (4 * dq + 2) * VTS + kp] = pack2(va.z, vb.z);
            sm[W_V + (4 * dq + 3) * VTS + kp] = pack2(va.w, vb.w);
        }
        __syncthreads();   // B2: Kh/Vt visible

        // ---- QK^T on own 64-key half: S(16x64), kk = 8 k16-steps ----
        float Sa[8][4];
#pragma unroll
        for (int n = 0; n < 8; ++n)
#pragma unroll
            for (int c = 0; c < 4; ++c) Sa[n][c] = 0.0f;
#pragma unroll
        for (int kk = 0; kk < 8; ++kk) {
            const uint32_t* qp = sm + W_Q + r0loc * QS + kk * 8 + t;
            uint32_t qa[4] = {qp[0], qp[8 * QS], qp[4], qp[8 * QS + 4]};
#pragma unroll
            for (int n = 0; n < 8; ++n) {
                const uint32_t* kb = sm + W_K + (ko + n * 8 + g) * QS + kk * 8 + t;
                mma16(Sa[n], qa, kb[0], kb[4]);
            }
        }

        // ---- causal mask (diag tile only; BK==BQ so local compare) ----
        if (kt == qt) {
#pragma unroll
            for (int n = 0; n < 8; ++n) {
                int c = ko + n * 8 + 2 * t;
                if (c     > r0loc) Sa[n][0] = -1e30f;
                if (c + 1 > r0loc) Sa[n][1] = -1e30f;
                if (c     > r1loc) Sa[n][2] = -1e30f;
                if (c + 1 > r1loc) Sa[n][3] = -1e30f;
            }
        }

        // ---- private online softmax ----
        float t0 = -1e30f, t1 = -1e30f;
#pragma unroll
        for (int n = 0; n < 8; ++n) {
            t0 = fmaxf(t0, fmaxf(Sa[n][0], Sa[n][1]));
            t1 = fmaxf(t1, fmaxf(Sa[n][2], Sa[n][3]));
        }
        t0 = fmaxf(t0, __shfl_xor_sync(0xffffffffu, t0, 1));
        t0 = fmaxf(t0, __shfl_xor_sync(0xffffffffu, t0, 2));
        t1 = fmaxf(t1, __shfl_xor_sync(0xffffffffu, t1, 1));
        t1 = fmaxf(t1, __shfl_xor_sync(0xffffffffu, t1, 2));
        const float M0 = fmaxf(mr0, t0), M1 = fmaxf(mr1, t1);
        const float f0 = __expf(mr0 - M0), f1 = __expf(mr1 - M1);
        mr0 = M0; mr1 = M1;

        // ---- exp + P (warp-private, f16x2 key-pairs) ----
        float s0 = 0.0f, s1 = 0.0f;
#pragma unroll
        for (int n = 0; n < 8; ++n) {
            float p00 = __expf(Sa[n][0] - M0), p01 = __expf(Sa[n][1] - M0);
            float p10 = __expf(Sa[n][2] - M1), p11 = __expf(Sa[n][3] - M1);
            s0 += p00 + p01; s1 += p10 + p11;
            sm[pw + g * PSTR + n * 4 + t]       = pack2(p00, p01);
            sm[pw + (g + 8) * PSTR + n * 4 + t] = pack2(p10, p11);
        }
        s0 += __shfl_xor_sync(0xffffffffu, s0, 1);
        s0 += __shfl_xor_sync(0xffffffffu, s0, 2);
        s1 += __shfl_xor_sync(0xffffffffu, s1, 1);
        s1 += __shfl_xor_sync(0xffffffffu, s1, 2);
        lr0 = lr0 * f0 + s0;
        lr1 = lr1 * f1 + s1;
        __syncwarp();      // P is warp-private

        // ---- rescale O; PV on own 64-key half (kk2 = 4 k16-steps) ----
#pragma unroll
        for (int n = 0; n < 16; ++n) {
            Oa[n][0] *= f0; Oa[n][1] *= f0; Oa[n][2] *= f1; Oa[n][3] *= f1;
        }
#pragma unroll
        for (int kk = 0; kk < 4; ++kk) {
            const uint32_t* pp = sm + pw + g * PSTR + kk * 8 + t;
            uint32_t pa[4] = {pp[0], pp[8 * PSTR], pp[4], pp[8 * PSTR + 4]};
            const uint32_t koff = (uint32_t)(wk * 32 + kk * 8 + t);
#pragma unroll
            for (int n = 0; n < 16; ++n) {
                const uint32_t* vb = sm + W_V + (n * 8 + g) * VTS + koff;
                mma16(Oa[n], pa, vb[0], vb[4]);
            }
        }
    }

    // ---- epilogue: two-way flash merge of the private halves ----
    __syncthreads();       // main loop done; Qh/Kh dead -> reuse as Ored
    if (wk == 1) {
#pragma unroll
        for (int n = 0; n < 16; ++n) {
            float* o0 = Ored + r0loc * 132 + n * 8 + 2 * t;
            o0[0] = Oa[n][0]; o0[1] = Oa[n][1];
            float* o1 = Ored + r1loc * 132 + n * 8 + 2 * t;
            o1[0] = Oa[n][2]; o1[1] = Oa[n][3];
        }
        if (t == 0) {
            mlx[2 * r0loc] = mr0; mlx[2 * r0loc + 1] = lr0;
            mlx[2 * r1loc] = mr1; mlx[2 * r1loc + 1] = lr1;
        }
    }
    __syncthreads();
    if (wk == 0) {
        const float m1a = mlx[2 * r0loc], l1a = mlx[2 * r0loc + 1];
        const float m1b = mlx[2 * r1loc], l1b = mlx[2 * r1loc + 1];
        const float Ma = fmaxf(mr0, m1a), Mb = fmaxf(mr1, m1b);
        const float c0a = __expf(mr0 - Ma), c1a = __expf(m1a - Ma);
        const float c0b = __expf(mr1 - Mb), c1b = __expf(m1b - Mb);
        const float inva = 1.0f / (lr0 * c0a + l1a * c1a);
        const float invb = 1.0f / (lr1 * c0b + l1b * c1b);
        const int q0g = qt * BQ + r0loc, q1g = qt * BQ + r1loc;
        float* ob0 = out + (((size_t)b * S_ + q0g) * HQ_ + h) * D_;
        float* ob1 = out + (((size_t)b * S_ + q1g) * HQ_ + h) * D_;
#pragma unroll
        for (int n = 0; n < 16; ++n) {
            int col = n * 8 + 2 * t;
            float2 o0, o1;
            o0.x = (Oa[n][0] * c0a + Ored[r0loc * 132 + col]     * c1a) * inva;
            o0.y = (Oa[n][1] * c0a + Ored[r0loc * 132 + col + 1] * c1a) * inva;
            o1.x = (Oa[n][2] * c0b + Ored[r1loc * 132 + col]     * c1b) * invb;
            o1.y = (Oa[n][3] * c0b + Ored[r1loc * 132 + col + 1] * c1b) * invb;
            *reinterpret_cast<float2*>(ob0 + col) = o0;
            *reinterpret_cast<float2*>(ob1 + col) = o1;
        }
    }
}

// -------------------------------------------------------------------------
extern "C" void kernel_launch(void* const* d_in, const int* in_sizes, int n_in,
                              void* d_out, int out_size) {
    const float* xq    = (const float*)d_in[0];
    const float* xk    = (const float*)d_in[1];
    const float* xv    = (const float*)d_in[2];
    const float* kvbuf = (const float*)d_in[3];
    const int*   idx   = (const int*)d_in[4];

    float* out   = (float*)d_out;
    float* kvout = out + (size_t)B_ * S_ * HQ_ * D_;

    cudaMemcpyAsync(kvout, kvbuf, (size_t)B_ * S_ * 2 * HKV_ * D_ * sizeof(float),
                    cudaMemcpyDeviceToDevice, 0);
    const int nvec = B_ * S_ * 2 * HKV_ * (D_ / 4);
    kv_scatter_kernel<<<(nvec + 255) / 256, 256>>>(xk, xv, idx, kvout);

    const int smem_bytes = W_TOT * (int)sizeof(uint32_t);   // 142,336
    cudaFuncSetAttribute(attn_mma,
                         cudaFuncAttributeMaxDynamicSharedMemorySize, smem_bytes);
    attn_mma<<<dim3(S_ / BQ, HQ_, B_), NT, smem_bytes>>>(xq, xk, xv, out);
}

// round 11
// speedup vs baseline: 2.1639x; 1.2946x over previous
#include <cuda_runtime.h>
#include <cstdint>

#define B_    2
#define S_    1024
#define HQ_   32
#define HKV_  8
#define D_    128
#define BQ    128
#define BK    128
#define NT    512
#define QS    68     // row stride in u32 words for Q/K/V tiles (64 + 4 pad)
#define PSTR  36

// smem u32-word offsets
#define W_Q    0         // 128*68 = 8704
#define W_K0   8704
#define W_K1   17408
#define W_V0   26112
#define W_V1   34816
#define W_P    43520     // 16 warps * 16 rows * 36 = 9216
#define W_MLX  52736     // 256
#define W_TOT  52992     // 211,968 bytes

// preconverted fp16 K and transposed V (layouts match the smem tiles)
__device__ uint32_t g_Kh[2 * 8 * 1024 * 64];   // [bh][key][d-pair]   4 MB
__device__ uint32_t g_Vt[2 * 8 * 128 * 512];   // [bh][d][key-pair]   4 MB

static __device__ __forceinline__ uint32_t pack2(float lo, float hi) {
    uint32_t d;
    asm("cvt.rn.f16x2.f32 %0, %1, %2;" : "=r"(d) : "f"(hi), "f"(lo));
    return d;
}
static __device__ __forceinline__ void mma16(float* d, const uint32_t* a,
                                             uint32_t b0, uint32_t b1) {
    asm volatile(
        "mma.sync.aligned.m16n8k16.row.col.f32.f16.f16.f32 "
        "{%0,%1,%2,%3}, {%4,%5,%6,%7}, {%8,%9}, {%0,%1,%2,%3};"
        : "+f"(d[0]), "+f"(d[1]), "+f"(d[2]), "+f"(d[3])
        : "r"(a[0]), "r"(a[1]), "r"(a[2]), "r"(a[3]), "r"(b0), "r"(b1));
}
static __device__ __forceinline__ uint32_t smem_u32(const void* p) {
    uint32_t a;
    asm("{ .reg .u64 t; cvta.to.shared.u64 t, %1; cvt.u32.u64 %0, t; }"
        : "=r"(a) : "l"(p));
    return a;
}
static __device__ __forceinline__ void cp16(uint32_t dst, const uint32_t* src) {
    asm volatile("cp.async.cg.shared.global [%0], [%1], 16;"
                 :: "r"(dst), "l"(src) : "memory");
}

// -------------------------------------------------------------------------
// KV-cache scatter (unchanged — negligible)
// -------------------------------------------------------------------------
__global__ void kv_scatter_kernel(const float* __restrict__ xk,
                                  const float* __restrict__ xv,
                                  const int* __restrict__ idx,
                                  float* __restrict__ kvout) {
    int t = blockIdx.x * blockDim.x + threadIdx.x;
    const int total = B_ * S_ * 2 * HKV_ * (D_ / 4);
    if (t >= total) return;
    int d4 = t & 31;
    int hh = (t >> 5) & 15;
    int i  = t >> 9;
    float4 v;
    if (hh < HKV_)
        v = reinterpret_cast<const float4*>(xk)[(i * HKV_ + hh) * 32 + d4];
    else
        v = reinterpret_cast<const float4*>(xv)[(i * HKV_ + (hh - HKV_)) * 32 + d4];
    int row = idx[i];
    reinterpret_cast<float4*>(kvout)[((size_t)row * 16 + hh) * 32 + d4] = v;
}

// -------------------------------------------------------------------------
// Prep 1: K fp32 -> fp16 d-pairs, [bh][key][d-pair word]
// -------------------------------------------------------------------------
__global__ void kh_prep(const float* __restrict__ xk) {
    int t = blockIdx.x * 256 + threadIdx.x;      // 524,288 tasks
    int d4 = t & 31, key = (t >> 5) & 1023, bh = t >> 15;
    int b = bh >> 3, hk = bh & 7;
    float4 v = *reinterpret_cast<const float4*>(
        xk + (((size_t)b * S_ + key) * HKV_ + hk) * D_ + 4 * d4);
    uint2 u;
    u.x = pack2(v.x, v.y);
    u.y = pack2(v.z, v.w);
    *reinterpret_cast<uint2*>(g_Kh + ((size_t)bh * 1024 + key) * 64 + 2 * d4) = u;
}

// -------------------------------------------------------------------------
// Prep 2: V fp32 -> fp16 transposed, [bh][d][key-pair word] (smem transpose)
// CTA = (bh, 128-key block). 256 threads.
// -------------------------------------------------------------------------
__global__ void vt_prep(const float* __restrict__ xv) {
    __shared__ uint32_t ts[128][65];
    const int bh = blockIdx.x, kpb = blockIdx.y;
    const int b = bh >> 3, hk = bh & 7;
    const int tid = threadIdx.x;
#pragma unroll
    for (int i = 0; i < 8; ++i) {
        int it = tid + i * 256;                  // (kp 0..63, d4 0..31)
        int kp = it & 63, d4 = it >> 6;
        int k0 = kpb * 128 + 2 * kp;
        const float4 a = *reinterpret_cast<const float4*>(
            xv + (((size_t)b * S_ + k0) * HKV_ + hk) * D_ + 4 * d4);
        const float4 c = *reinterpret_cast<const float4*>(
            xv + (((size_t)b * S_ + k0 + 1) * HKV_ + hk) * D_ + 4 * d4);
        ts[4 * d4 + 0][kp] = pack2(a.x, c.x);
        ts[4 * d4 + 1][kp] = pack2(a.y, c.y);
        ts[4 * d4 + 2][kp] = pack2(a.z, c.z);
        ts[4 * d4 + 3][kp] = pack2(a.w, c.w);
    }
    __syncthreads();
#pragma unroll
    for (int i = 0; i < 32; ++i) {
        int it = tid + i * 256;                  // (d 0..127, kp 0..63)
        int d = it >> 6, kp = it & 63;
        g_Vt[((size_t)bh * 128 + d) * 512 + kpb * 64 + kp] = ts[d][kp];
    }
}

// -------------------------------------------------------------------------
// fp16 m16n8k16 split-K flash attention, cp.async double-buffered K/V.
// Compute identical to R10; tiles stream from preconverted g_Kh/g_Vt.
// -------------------------------------------------------------------------
__global__ __launch_bounds__(NT, 1)
void attn_mma(const float* __restrict__ xq, float* __restrict__ out) {
    extern __shared__ uint32_t sm[];
    float* mlx  = (float*)(sm + W_MLX);
    float* Ored = (float*)(sm + W_Q);     // epilogue alias

    const int tid = threadIdx.x, w = tid >> 5, lane = tid & 31;
    const int wq = w >> 1, wk = w & 1;
    const int g = lane >> 2, t = lane & 3;
    const int qt = (S_ / BQ - 1) - blockIdx.x;   // big tiles first
    const int h = blockIdx.y, b = blockIdx.z, hk = h >> 2;
    const int bh = b * 8 + hk;
    const int m0 = wq * 16, ko = wk * 64;
    const int r0loc = m0 + g, r1loc = m0 + g + 8;
    const float scale = 0.08838834764831845f;    // 1/sqrt(128)
    const uint32_t pw = W_P + w * 576;
    const uint32_t sb = smem_u32(sm);

    // ---- Q tile: global -> f16x2 (scaled) ----
#pragma unroll
    for (int i = 0; i < 8; ++i) {
        int it = tid + i * NT;
        int r = it >> 5, c4 = it & 31;
        float4 v = *reinterpret_cast<const float4*>(
            xq + ((((size_t)b * S_ + (size_t)qt * BQ + r) * HQ_ + h) * D_ + c4 * 4));
        uint2 u;
        u.x = pack2(v.x * scale, v.y * scale);
        u.y = pack2(v.z * scale, v.w * scale);
        *reinterpret_cast<uint2*>(sm + W_Q + r * QS + c4 * 2) = u;
    }

    const uint32_t* khb = g_Kh + (size_t)bh * 1024 * 64;
    const uint32_t* vtb = g_Vt + (size_t)bh * 128 * 512;

    // tile issue: 4096 16B chunks (2048 K + 2048 V), 8 per thread
    auto issue = [&](int kt_, uint32_t kbuf, uint32_t vbuf) {
        const uint32_t* ks = khb + (size_t)kt_ * 128 * 64;
        const uint32_t* vs = vtb + kt_ * 64;
#pragma unroll
        for (int i = 0; i < 4; ++i) {
            int idx = tid + i * NT;
            int r = idx >> 4, c16 = idx & 15;
            cp16(sb + (kbuf + r * QS + c16 * 4) * 4, ks + r * 64 + c16 * 4);
        }
#pragma unroll
        for (int i = 0; i < 4; ++i) {
            int idx = tid + i * NT;
            int r = idx >> 4, c16 = idx & 15;
            cp16(sb + (vbuf + r * QS + c16 * 4) * 4, vs + (size_t)r * 512 + c16 * 4);
        }
        asm volatile("cp.async.commit_group;" ::: "memory");
    };

    issue(0, W_K0, W_V0);    // prologue

    float Oa[16][4];
#pragma unroll
    for (int n = 0; n < 16; ++n)
#pragma unroll
        for (int c = 0; c < 4; ++c) Oa[n][c] = 0.0f;
    float mr0 = -1e30f, mr1 = -1e30f, lr0 = 0.0f, lr1 = 0.0f;

    for (int kt = 0; kt <= qt; ++kt) {
        const int p = kt & 1;
        const uint32_t kbuf = p ? W_K1 : W_K0;
        const uint32_t vbuf = p ? W_V1 : W_V0;

        if (kt > 0) __syncthreads();   // B1: prev compute done with buf[1-p]
        if (kt < qt) {
            issue(kt + 1, p ? W_K0 : W_K1, p ? W_V0 : W_V1);
            asm volatile("cp.async.wait_group 1;" ::: "memory");
        } else {
            asm volatile("cp.async.wait_group 0;" ::: "memory");
        }
        __syncthreads();               // B2: tile kt visible (kt=0: + Q stores)

        // ---- QK^T on own 64-key half: S(16x64), 8 k16-steps ----
        float Sa[8][4];
#pragma unroll
        for (int n = 0; n < 8; ++n)
#pragma unroll
            for (int c = 0; c < 4; ++c) Sa[n][c] = 0.0f;
#pragma unroll
        for (int kk = 0; kk < 8; ++kk) {
            const uint32_t* qp = sm + W_Q + r0loc * QS + kk * 8 + t;
            uint32_t qa[4] = {qp[0], qp[8 * QS], qp[4], qp[8 * QS + 4]};
#pragma unroll
            for (int n = 0; n < 8; ++n) {
                const uint32_t* kb = sm + kbuf + (ko + n * 8 + g) * QS + kk * 8 + t;
                mma16(Sa[n], qa, kb[0], kb[4]);
            }
        }

        // ---- causal mask (diag tile only) ----
        if (kt == qt) {
#pragma unroll
            for (int n = 0; n < 8; ++n) {
                int c = ko + n * 8 + 2 * t;
                if (c     > r0loc) Sa[n][0] = -1e30f;
                if (c + 1 > r0loc) Sa[n][1] = -1e30f;
                if (c     > r1loc) Sa[n][2] = -1e30f;
                if (c + 1 > r1loc) Sa[n][3] = -1e30f;
            }
        }

        // ---- private online softmax ----
        float t0 = -1e30f, t1 = -1e30f;
#pragma unroll
        for (int n = 0; n < 8; ++n) {
            t0 = fmaxf(t0, fmaxf(Sa[n][0], Sa[n][1]));
            t1 = fmaxf(t1, fmaxf(Sa[n][2], Sa[n][3]));
        }
        t0 = fmaxf(t0, __shfl_xor_sync(0xffffffffu, t0, 1));
        t0 = fmaxf(t0, __shfl_xor_sync(0xffffffffu, t0, 2));
        t1 = fmaxf(t1, __shfl_xor_sync(0xffffffffu, t1, 1));
        t1 = fmaxf(t1, __shfl_xor_sync(0xffffffffu, t1, 2));
        const float M0 = fmaxf(mr0, t0), M1 = fmaxf(mr1, t1);
        const float f0 = __expf(mr0 - M0), f1 = __expf(mr1 - M1);
        mr0 = M0; mr1 = M1;

        float s0 = 0.0f, s1 = 0.0f;
#pragma unroll
        for (int n = 0; n < 8; ++n) {
            float p00 = __expf(Sa[n][0] - M0), p01 = __expf(Sa[n][1] - M0);
            float p10 = __expf(Sa[n][2] - M1), p11 = __expf(Sa[n][3] - M1);
            s0 += p00 + p01; s1 += p10 + p11;
            sm[pw + g * PSTR + n * 4 + t]       = pack2(p00, p01);
            sm[pw + (g + 8) * PSTR + n * 4 + t] = pack2(p10, p11);
        }
        s0 += __shfl_xor_sync(0xffffffffu, s0, 1);
        s0 += __shfl_xor_sync(0xffffffffu, s0, 2);
        s1 += __shfl_xor_sync(0xffffffffu, s1, 1);
        s1 += __shfl_xor_sync(0xffffffffu, s1, 2);
        lr0 = lr0 * f0 + s0;
        lr1 = lr1 * f1 + s1;
        __syncwarp();

        // ---- rescale O; PV on own 64-key half (4 k16-steps) ----
#pragma unroll
        for (int n = 0; n < 16; ++n) {
            Oa[n][0] *= f0; Oa[n][1] *= f0; Oa[n][2] *= f1; Oa[n][3] *= f1;
        }
#pragma unroll
        for (int kk = 0; kk < 4; ++kk) {
            const uint32_t* pp = sm + pw + g * PSTR + kk * 8 + t;
            uint32_t pa[4] = {pp[0], pp[8 * PSTR], pp[4], pp[8 * PSTR + 4]};
            const uint32_t koff = (uint32_t)(wk * 32 + kk * 8 + t);
#pragma unroll
            for (int n = 0; n < 16; ++n) {
                const uint32_t* vb = sm + vbuf + (n * 8 + g) * QS + koff;
                mma16(Oa[n], pa, vb[0], vb[4]);
            }
        }
    }

    // ---- epilogue: two-way flash merge of the private halves ----
    __syncthreads();
    if (wk == 1) {
#pragma unroll
        for (int n = 0; n < 16; ++n) {
            float* o0 = Ored + r0loc * 132 + n * 8 + 2 * t;
            o0[0] = Oa[n][0]; o0[1] = Oa[n][1];
            float* o1 = Ored + r1loc * 132 + n * 8 + 2 * t;
            o1[0] = Oa[n][2]; o1[1] = Oa[n][3];
        }
        if (t == 0) {
            mlx[2 * r0loc] = mr0; mlx[2 * r0loc + 1] = lr0;
            mlx[2 * r1loc] = mr1; mlx[2 * r1loc + 1] = lr1;
        }
    }
    __syncthreads();
    if (wk == 0) {
        const float m1a = mlx[2 * r0loc], l1a = mlx[2 * r0loc + 1];
        const float m1b = mlx[2 * r1loc], l1b = mlx[2 * r1loc + 1];
        const float Ma = fmaxf(mr0, m1a), Mb = fmaxf(mr1, m1b);
        const float c0a = __expf(mr0 - Ma), c1a = __expf(m1a - Ma);
        const float c0b = __expf(mr1 - Mb), c1b = __expf(m1b - Mb);
        const float inva = 1.0f / (lr0 * c0a + l1a * c1a);
        const float invb = 1.0f / (lr1 * c0b + l1b * c1b);
        const int q0g = qt * BQ + r0loc, q1g = qt * BQ + r1loc;
        float* ob0 = out + (((size_t)b * S_ + q0g) * HQ_ + h) * D_;
        float* ob1 = out + (((size_t)b * S_ + q1g) * HQ_ + h) * D_;
#pragma unroll
        for (int n = 0; n < 16; ++n) {
            int col = n * 8 + 2 * t;
            float2 o0, o1;
            o0.x = (Oa[n][0] * c0a + Ored[r0loc * 132 + col]     * c1a) * inva;
            o0.y = (Oa[n][1] * c0a + Ored[r0loc * 132 + col + 1] * c1a) * inva;
            o1.x = (Oa[n][2] * c0b + Ored[r1loc * 132 + col]     * c1b) * invb;
            o1.y = (Oa[n][3] * c0b + Ored[r1loc * 132 + col + 1] * c1b) * invb;
            *reinterpret_cast<float2*>(ob0 + col) = o0;
            *reinterpret_cast<float2*>(ob1 + col) = o1;
        }
    }
}

// -------------------------------------------------------------------------
extern "C" void kernel_launch(void* const* d_in, const int* in_sizes, int n_in,
                              void* d_out, int out_size) {
    const float* xq    = (const float*)d_in[0];
    const float* xk    = (const float*)d_in[1];
    const float* xv    = (const float*)d_in[2];
    const float* kvbuf = (const float*)d_in[3];
    const int*   idx   = (const int*)d_in[4];

    float* out   = (float*)d_out;
    float* kvout = out + (size_t)B_ * S_ * HQ_ * D_;

    cudaMemcpyAsync(kvout, kvbuf, (size_t)B_ * S_ * 2 * HKV_ * D_ * sizeof(float),
                    cudaMemcpyDeviceToDevice, 0);
    const int nvec = B_ * S_ * 2 * HKV_ * (D_ / 4);
    kv_scatter_kernel<<<(nvec + 255) / 256, 256>>>(xk, xv, idx, kvout);

    kh_prep<<<2048, 256>>>(xk);
    vt_prep<<<dim3(16, 8), 256>>>(xv);

    const int smem_bytes = W_TOT * (int)sizeof(uint32_t);   // 211,968
    cudaFuncSetAttribute(attn_mma,
                         cudaFuncAttributeMaxDynamicSharedMemorySize, smem_bytes);
    attn_mma<<<dim3(S_ / BQ, HQ_, B_), NT, smem_bytes>>>(xq, out);
}